// round 14
// baseline (speedup 1.0000x reference)
#include <cuda_runtime.h>
#include <cuda_fp16.h>
#include <math.h>
#include <stdint.h>

#define BATCH 2
#define SEQ   2048
#define SEQE  (SEQ + 64)   /* emb rows padded with 64 zero rows */
#define DM    1024
#define NHEAD 16
#define HS    64
#define FQ    256
#define BN3   3072   /* 3*NHEAD*HS */

// ---------------- scratch (device globals; no allocations allowed) ----------
__device__ __half g_inph[BATCH*SEQ*DM];       // fp16 copy of input
__device__ __half g_wh[DM*BN3];               // fp16 copy of qkv weight
__device__ __half g_wkh[DM*DM];               // fp16 copy of out_kernel
__device__ __half g_Qh[BATCH*NHEAD*SEQ*HS];   // [bn][s][h]
__device__ __half g_Kh[BATCH*NHEAD*SEQ*HS];   // [bn][s][h]
__device__ __half g_Vh[BATCH*NHEAD*SEQ*HS];   // plain [bn][s][h]
__device__ __half g_embh[NHEAD*SEQE*HS];      // [n][d][h], rows [SEQ,SEQE) zero
__device__ __half g_Oh[BATCH*SEQ*NHEAD*HS];   // attention output, fp16

// ---------------- helpers -----------------------------------------------------
__device__ __forceinline__ void mma16(float c[4], const uint32_t a[4], const uint32_t b[2]) {
    asm volatile(
      "mma.sync.aligned.m16n8k16.row.col.f32.f16.f16.f32 "
      "{%0,%1,%2,%3}, {%4,%5,%6,%7}, {%8,%9}, {%0,%1,%2,%3};"
      : "+f"(c[0]), "+f"(c[1]), "+f"(c[2]), "+f"(c[3])
      : "r"(a[0]), "r"(a[1]), "r"(a[2]), "r"(a[3]), "r"(b[0]), "r"(b[1]));
}
__device__ __forceinline__ void ldsm4(uint32_t r[4], uint32_t saddr) {
    asm volatile("ldmatrix.sync.aligned.m8n8.x4.shared.b16 {%0,%1,%2,%3}, [%4];"
      : "=r"(r[0]), "=r"(r[1]), "=r"(r[2]), "=r"(r[3]) : "r"(saddr));
}
__device__ __forceinline__ void ldsm4t(uint32_t r[4], uint32_t saddr) {
    asm volatile("ldmatrix.sync.aligned.m8n8.x4.trans.shared.b16 {%0,%1,%2,%3}, [%4];"
      : "=r"(r[0]), "=r"(r[1]), "=r"(r[2]), "=r"(r[3]) : "r"(saddr));
}
__device__ __forceinline__ void cpa16(uint32_t dst, const void* src) {
    asm volatile("cp.async.cg.shared.global [%0], [%1], 16;" :: "r"(dst), "l"(src));
}
__device__ __forceinline__ void cpa_commit() { asm volatile("cp.async.commit_group;"); }
__device__ __forceinline__ void cpa_wait0()  { asm volatile("cp.async.wait_group 0;"); }
__device__ __forceinline__ void cpa_wait1()  { asm volatile("cp.async.wait_group 1;"); }
__device__ __forceinline__ uint32_t h2u(__half2 h) { return *(uint32_t*)&h; }

extern __shared__ uint32_t smw[];

// ---------------- 0) fp32 -> fp16 converter ----------------------------------
__global__ __launch_bounds__(256) void cvt_kernel(
    const float4* __restrict__ src, uint2* __restrict__ dst, int n4)
{
    int i = blockIdx.x * 256 + threadIdx.x;
    if (i < n4) {
        float4 v = src[i];
        uint2 o;
        o.x = h2u(__floats2half2_rn(v.x, v.y));
        o.y = h2u(__floats2half2_rn(v.z, v.w));
        dst[i] = o;
    }
}

// ---------------- 1) QKV projection: cp.async double-buffered ----------------
// dyn SMEM (halves): A[2] @ {0, 9216} (128x72 each), B[2] @ {18432, 27136}
// (64x136 each) -> 35840 halves = 71680 B
__global__ __launch_bounds__(256) void qkv_kernel(const float* __restrict__ qb)
{
    const int tid = threadIdx.x, lane = tid & 31, wid = tid >> 5;
    const int g = lane >> 2, tg = lane & 3;
    const int warpN = wid & 1, warpM = wid >> 1;     // warp tile 32x64
    const int m0 = blockIdx.y * 128, n0 = blockIdx.x * 128;
    const uint32_t aS = (uint32_t)__cvta_generic_to_shared(smw);
    const int l15 = lane & 15, lh = (lane & 16) >> 1;

    // prologue: fill stage 0
    #pragma unroll
    for (int t = 0; t < 4; t++) {
        int e = tid + t * 256;
        int r = e >> 3, c = (e & 7) * 8;
        cpa16(aS + (r * 72 + c) * 2, &g_inph[(size_t)(m0 + r) * DM + c]);
    }
    #pragma unroll
    for (int t = 0; t < 4; t++) {
        int e = tid + t * 256;
        int r = e >> 4, c = (e & 15) * 8;
        cpa16(aS + (18432 + r * 136 + c) * 2, &g_wh[(size_t)r * BN3 + n0 + c]);
    }
    cpa_commit();

    float acc[2][8][4] = {};
    for (int it = 0; it < 16; it++) {
        const int buf = it & 1;
        if (it < 15) {
            const int k0n = (it + 1) * 64, bn_ = buf ^ 1;
            #pragma unroll
            for (int t = 0; t < 4; t++) {
                int e = tid + t * 256;
                int r = e >> 3, c = (e & 7) * 8;
                cpa16(aS + (bn_ * 9216 + r * 72 + c) * 2,
                      &g_inph[(size_t)(m0 + r) * DM + k0n + c]);
            }
            #pragma unroll
            for (int t = 0; t < 4; t++) {
                int e = tid + t * 256;
                int r = e >> 4, c = (e & 15) * 8;
                cpa16(aS + (18432 + bn_ * 8704 + r * 136 + c) * 2,
                      &g_wh[(size_t)(k0n + r) * BN3 + n0 + c]);
            }
            cpa_commit();
            cpa_wait1();
        } else {
            cpa_wait0();
        }
        __syncthreads();

        const uint32_t aA = aS + buf * 9216 * 2;
        const uint32_t aB = aS + (18432 + buf * 8704) * 2;
        #pragma unroll
        for (int ks = 0; ks < 4; ks++) {
            uint32_t af[2][4];
            #pragma unroll
            for (int i = 0; i < 2; i++) {
                int mr = warpM * 32 + i * 16;
                ldsm4(af[i], aA + ((mr + l15) * 72 + ks * 16 + lh) * 2);
            }
            #pragma unroll
            for (int jp = 0; jp < 4; jp++) {
                int nj = warpN * 64 + jp * 16;
                uint32_t bq[4];
                ldsm4t(bq, aB + ((ks * 16 + l15) * 136 + nj + lh) * 2);
                mma16(acc[0][2*jp],   af[0], bq);
                mma16(acc[0][2*jp+1], af[0], bq + 2);
                mma16(acc[1][2*jp],   af[1], bq);
                mma16(acc[1][2*jp+1], af[1], bq + 2);
            }
        }
        __syncthreads();
    }

    const float qscale = powf(3.0f * DM * NHEAD * HS, -0.25f);
    #pragma unroll
    for (int i = 0; i < 2; i++) {
        #pragma unroll
        for (int j = 0; j < 8; j++) {
            #pragma unroll
            for (int cr = 0; cr < 4; cr++) {
                int m = m0 + warpM * 32 + i * 16 + g + (cr >> 1) * 8;
                int c = n0 + warpN * 64 + j * 8 + tg * 2 + (cr & 1);
                int b = m >> 11, s = m & (SEQ - 1);
                int A = c >> 10, n = (c >> 6) & 15, h = c & 63;
                float v = acc[i][j][cr] * qscale;
                size_t bn = (size_t)(b * NHEAD + n);
                if (A == 0)
                    g_Qh[(bn * SEQ + s) * HS + h] = __float2half_rn(v + qb[n * HS + h]);
                else if (A == 1)
                    g_Kh[(bn * SEQ + s) * HS + h] = __float2half_rn(v);
                else
                    g_Vh[(bn * SEQ + s) * HS + h] = __float2half_rn(v);
            }
        }
    }
}

// ---------------- 2) relative-position embedding table (fp16 out) -----------
__global__ __launch_bounds__(256) void emb_kernel(const float* __restrict__ pos)
{
    __shared__ float ssin[FQ];
    const int s = blockIdx.x;
    const int tid = threadIdx.x;
    {
        int f = tid;
        double inv = pow(10000.0, -(double)((f >> 1) * 2) / (double)FQ);
        double ang = (double)s * inv;
        double v = (f & 1) ? cos(ang) : sin(ang);
        ssin[f] = (float)(1.4142135623730951 * v);
    }
    __syncthreads();

    int c4 = tid * 4;
    float a0 = 0.f, a1 = 0.f, a2 = 0.f, a3 = 0.f;
    for (int f = 0; f < FQ; f++) {
        float4 p = *reinterpret_cast<const float4*>(&pos[(size_t)f * (NHEAD * HS) + c4]);
        float sv = ssin[f];
        a0 += sv * p.x; a1 += sv * p.y; a2 += sv * p.z; a3 += sv * p.w;
    }
    const float pscale = 0.0625f;
    int n = c4 >> 6, h = c4 & 63;
    size_t base = ((size_t)n * SEQE + s) * HS + h;
    g_embh[base + 0] = __float2half_rn(a0 * pscale);
    g_embh[base + 1] = __float2half_rn(a1 * pscale);
    g_embh[base + 2] = __float2half_rn(a2 * pscale);
    g_embh[base + 3] = __float2half_rn(a3 * pscale);
}

// ---------------- 3) fused flash attention: async V, 3 barriers/iter --------
// SMEM word layout (dynamic), 20928 words = 83712 B (2 blocks/SM):
//   sQh   [64][36w]  persistent                @ 0
//   sKEh  [192][36w] (K rows 0-63, E 64-191)   @ 2304
//   sPB   [64][72]   fp32 banded pos panel     @ 9216
//   sPh   [64][36w]  P fp16 k-pair words       @ 13824
//   sVh[2] each [64][36w]                      @ 16128 / 18432
//   m_s/l_s/rs [64] each                       @ 20736
__global__ __launch_bounds__(256, 2) void attn_kernel()
{
    const int qt = (SEQ / 64 - 1) - blockIdx.x;   // longest blocks first
    const int bn = blockIdx.y;
    const int q0 = qt * 64;

    uint32_t* sQh  = smw;
    float*    sPB  = (float*)(smw + 9216);
    uint32_t* sPh  = smw + 13824;
    float*    m_s  = (float*)(smw + 20736);
    float*    l_s  = m_s + 64;
    float*    rs   = m_s + 128;

    const uint32_t* Qg = (const uint32_t*)g_Qh + (size_t)bn * SEQ * (HS/2);
    const __half*   Kg = g_Kh + (size_t)bn * SEQ * HS;
    const __half*   Vg = g_Vh + (size_t)bn * SEQ * HS;
    const int hd = bn & (NHEAD - 1);
    const __half*   Eg = g_embh + (size_t)hd * SEQE * HS;

    const uint32_t aQ  = (uint32_t)__cvta_generic_to_shared(sQh);
    const uint32_t aKE = aQ + 2304 * 4;
    const uint32_t aP  = aQ + 13824 * 4;
    const uint32_t aV0 = aQ + 16128 * 4;

    const int tid = threadIdx.x, lane = tid & 31, wid = tid >> 5;
    const int g = lane >> 2, tg = lane & 3;
    const int wMs = wid & 3, wNs = wid >> 2;   // QK: 4x2 grid, tile 16x96; PV 16x32
    const int l15 = lane & 15, l8 = lane & 8, lh = (lane & 16) >> 1;
    const int l7 = lane & 7;

    // load Q tile (h-pair words) + init state
    #pragma unroll
    for (int t = 0; t < 2; t++) {
        int e = tid + t * 256;
        int r = e >> 3, c = (e & 7) * 4;
        *(uint4*)&sQh[r * 36 + c] = *(const uint4*)&Qg[(size_t)(q0 + r) * (HS/2) + c];
    }
    if (tid < 64) { m_s[tid] = -1e30f; l_s[tid] = 0.f; }

    // prologue: prefetch KE(0) + V(0) into buffer 0
    {
        int dlo = q0 - 63; if (dlo < 0) dlo = 0;
        #pragma unroll
        for (int t = 0; t < 6; t++) {
            int e = tid + t * 256;
            int r = e >> 3, c8 = e & 7;
            const __half* src = (r < 64) ? Kg + (size_t)r * HS + c8 * 8
                                         : Eg + (size_t)(dlo + r - 64) * HS + c8 * 8;
            cpa16(aKE + (r * 36 + c8 * 4) * 4, src);
        }
        #pragma unroll
        for (int t = 0; t < 2; t++) {
            int e = tid + t * 256;
            int r = e >> 3, c8 = e & 7;
            cpa16(aV0 + (r * 36 + c8 * 4) * 4, Vg + (size_t)r * HS + c8 * 8);
        }
        cpa_commit();
    }

    float acc_o[4][4] = {};

    for (int kt = 0; kt <= qt; kt++) {
        const int k0 = kt * 64;
        int dlo = q0 - k0 - 63; if (dlo < 0) dlo = 0;
        const int base_off = q0 - k0 - 63 - dlo;   // 0 except diag tile (-63)

        cpa_wait0();
        __syncthreads();   // BAR-A: KE+V visible; prior PV done

        // ---- fused QK^T / Q@E^T HMMA: 64x192, warp tile 16x96, ldmatrix ----
        float acc_s[12][4] = {};
        #pragma unroll
        for (int ks = 0; ks < 4; ks++) {
            uint32_t af[4];
            ldsm4(af, aQ + ((wMs * 16 + l15) * 72 + ks * 16 + lh) * 2);
            #pragma unroll
            for (int jp = 0; jp < 6; jp++) {
                int nc0 = wNs * 96 + jp * 16;
                uint32_t bq[4];
                ldsm4(bq, aKE + ((nc0 + l7 + lh) * 72 + ks * 16 + l8) * 2);
                mma16(acc_s[2*jp],   af, bq);
                mma16(acc_s[2*jp+1], af, bq + 2);
            }
        }

        // ---- scatter positional cols (>=64) into banded sPB ----
        #pragma unroll
        for (int j = 0; j < 12; j++) {
            int colbase = wNs * 96 + j * 8;
            if (colbase + 7 < 64) continue;   // content-only n-tile (compile-time)
            #pragma unroll
            for (int cr = 0; cr < 4; cr++) {
                int row = wMs * 16 + g + (cr >> 1) * 8;
                int col = colbase + tg * 2 + (cr & 1);
                int b = (col - 64) - (base_off + row);
                if ((unsigned)b < 64u) sPB[row * 72 + b] = acc_s[j][cr];
            }
        }
        __syncthreads();   // BAR-B

        // ---- register softmax (wNs==0 warps own all content cols) ----
        if (wNs == 0) {
            const int r0 = wMs * 16 + g, r1 = r0 + 8;
            const int qq0 = q0 + r0, qq1 = q0 + r1;
            const bool diag = (kt == qt);
            const float m_old0 = m_s[r0], m_old1 = m_s[r1];
            float mx0 = -1e30f, mx1 = -1e30f;
            #pragma unroll
            for (int j = 0; j < 8; j++) {
                #pragma unroll
                for (int b2 = 0; b2 < 2; b2++) {
                    int c = j * 8 + tg * 2 + b2;
                    int k = k0 + c;
                    float x0 = (diag && k > qq0) ? -1e30f
                             : (acc_s[j][b2]     + sPB[r0 * 72 + 63 - c]) * 0.125f;
                    float x1 = (diag && k > qq1) ? -1e30f
                             : (acc_s[j][2 + b2] + sPB[r1 * 72 + 63 - c]) * 0.125f;
                    acc_s[j][b2] = x0; acc_s[j][2 + b2] = x1;
                    mx0 = fmaxf(mx0, x0); mx1 = fmaxf(mx1, x1);
                }
            }
            mx0 = fmaxf(mx0, __shfl_xor_sync(0xffffffffu, mx0, 1));
            mx0 = fmaxf(mx0, __shfl_xor_sync(0xffffffffu, mx0, 2));
            mx1 = fmaxf(mx1, __shfl_xor_sync(0xffffffffu, mx1, 1));
            mx1 = fmaxf(mx1, __shfl_xor_sync(0xffffffffu, mx1, 2));
            const float mn0 = fmaxf(m_old0, mx0);
            const float mn1 = fmaxf(m_old1, mx1);
            float s0 = 0.f, s1 = 0.f;
            #pragma unroll
            for (int j = 0; j < 8; j++) {
                float p00 = __expf(acc_s[j][0] - mn0);
                float p01 = __expf(acc_s[j][1] - mn0);
                float p10 = __expf(acc_s[j][2] - mn1);
                float p11 = __expf(acc_s[j][3] - mn1);
                s0 += p00 + p01; s1 += p10 + p11;
                sPh[r0 * 36 + 4 * j + tg] = h2u(__floats2half2_rn(p00, p01));
                sPh[r1 * 36 + 4 * j + tg] = h2u(__floats2half2_rn(p10, p11));
            }
            s0 += __shfl_xor_sync(0xffffffffu, s0, 1);
            s0 += __shfl_xor_sync(0xffffffffu, s0, 2);
            s1 += __shfl_xor_sync(0xffffffffu, s1, 1);
            s1 += __shfl_xor_sync(0xffffffffu, s1, 2);
            if (tg == 0) {
                float sc0 = __expf(m_old0 - mn0);
                float sc1 = __expf(m_old1 - mn1);
                rs[r0] = sc0; m_s[r0] = mn0; l_s[r0] = l_s[r0] * sc0 + s0;
                rs[r1] = sc1; m_s[r1] = mn1; l_s[r1] = l_s[r1] * sc1 + s1;
            }
        }
        __syncthreads();   // BAR-C: sPh/state ready; QK reads of sKEh done

        // ---- prefetch next KE + V tile (overlaps PV MMA below) ----
        if (kt < qt) {
            const int k0n = k0 + 64;
            int dlon = q0 - k0n - 63; if (dlon < 0) dlon = 0;
            #pragma unroll
            for (int t = 0; t < 6; t++) {
                int e = tid + t * 256;
                int r = e >> 3, c8 = e & 7;
                const __half* src = (r < 64) ? Kg + (size_t)(k0n + r) * HS + c8 * 8
                                             : Eg + (size_t)(dlon + r - 64) * HS + c8 * 8;
                cpa16(aKE + (r * 36 + c8 * 4) * 4, src);
            }
            const uint32_t aVn = aV0 + ((kt + 1) & 1) * 9216;
            #pragma unroll
            for (int t = 0; t < 2; t++) {
                int e = tid + t * 256;
                int r = e >> 3, c8 = e & 7;
                cpa16(aVn + (r * 36 + c8 * 4) * 4, Vg + (size_t)(k0n + r) * HS + c8 * 8);
            }
            cpa_commit();
        }

        // ---- rescale O accumulator, then P @ V (ldmatrix) ----
        {
            const uint32_t aV = aV0 + (kt & 1) * 9216;
            const float s0 = rs[wMs * 16 + g];
            const float s1 = rs[wMs * 16 + g + 8];
            #pragma unroll
            for (int j = 0; j < 4; j++) {
                acc_o[j][0] *= s0; acc_o[j][1] *= s0;
                acc_o[j][2] *= s1; acc_o[j][3] *= s1;
            }
            #pragma unroll
            for (int ks = 0; ks < 4; ks++) {
                uint32_t af[4];
                ldsm4(af, aP + ((wMs * 16 + l15) * 72 + ks * 16 + lh) * 2);
                #pragma unroll
                for (int jp = 0; jp < 2; jp++) {
                    int nj = wNs * 32 + jp * 16;
                    uint32_t bq[4];
                    ldsm4t(bq, aV + ((ks * 16 + l15) * 72 + nj + lh) * 2);
                    mma16(acc_o[2*jp],   af, bq);
                    mma16(acc_o[2*jp+1], af, bq + 2);
                }
            }
        }
    }

    // ---- epilogue: divide by l, store fp16 ----
    const int b = bn >> 4, n = bn & 15;
    const float inv0 = 1.f / l_s[wMs * 16 + g];
    const float inv1 = 1.f / l_s[wMs * 16 + g + 8];
    #pragma unroll
    for (int j = 0; j < 4; j++) {
        #pragma unroll
        for (int cr = 0; cr < 4; cr++) {
            int q = q0 + wMs * 16 + g + (cr >> 1) * 8;
            int h = wNs * 32 + j * 8 + tg * 2 + (cr & 1);
            g_Oh[(((size_t)b * SEQ + q) * NHEAD + n) * HS + h] =
                __float2half_rn(acc_o[j][cr] * ((cr >> 1) ? inv1 : inv0));
        }
    }
}

// ---------------- 4) out = O @ (out_kernel*scale) + bias, double-buffered ---
__global__ __launch_bounds__(256) void proj_kernel(
    const float* __restrict__ bias, float* __restrict__ out)
{
    const int tid = threadIdx.x, lane = tid & 31, wid = tid >> 5;
    const int g = lane >> 2, tg = lane & 3;
    const int warpN = wid & 1, warpM = wid >> 1;
    const int m0 = blockIdx.y * 128, n0 = blockIdx.x * 128;
    const uint32_t aS = (uint32_t)__cvta_generic_to_shared(smw);
    const int l15 = lane & 15, lh = (lane & 16) >> 1;

    #pragma unroll
    for (int t = 0; t < 4; t++) {
        int e = tid + t * 256;
        int r = e >> 3, c = (e & 7) * 8;
        cpa16(aS + (r * 72 + c) * 2, &g_Oh[(size_t)(m0 + r) * DM + c]);
    }
    #pragma unroll
    for (int t = 0; t < 4; t++) {
        int e = tid + t * 256;
        int r = e >> 4, c = (e & 15) * 8;
        cpa16(aS + (18432 + r * 136 + c) * 2, &g_wkh[(size_t)r * DM + n0 + c]);
    }
    cpa_commit();

    float acc[2][8][4] = {};
    for (int it = 0; it < 16; it++) {
        const int buf = it & 1;
        if (it < 15) {
            const int k0n = (it + 1) * 64, bn_ = buf ^ 1;
            #pragma unroll
            for (int t = 0; t < 4; t++) {
                int e = tid + t * 256;
                int r = e >> 3, c = (e & 7) * 8;
                cpa16(aS + (bn_ * 9216 + r * 72 + c) * 2,
                      &g_Oh[(size_t)(m0 + r) * DM + k0n + c]);
            }
            #pragma unroll
            for (int t = 0; t < 4; t++) {
                int e = tid + t * 256;
                int r = e >> 4, c = (e & 15) * 8;
                cpa16(aS + (18432 + bn_ * 8704 + r * 136 + c) * 2,
                      &g_wkh[(size_t)(k0n + r) * DM + n0 + c]);
            }
            cpa_commit();
            cpa_wait1();
        } else {
            cpa_wait0();
        }
        __syncthreads();

        const uint32_t aA = aS + buf * 9216 * 2;
        const uint32_t aB = aS + (18432 + buf * 8704) * 2;
        #pragma unroll
        for (int ks = 0; ks < 4; ks++) {
            uint32_t af[2][4];
            #pragma unroll
            for (int i = 0; i < 2; i++) {
                int mr = warpM * 32 + i * 16;
                ldsm4(af[i], aA + ((mr + l15) * 72 + ks * 16 + lh) * 2);
            }
            #pragma unroll
            for (int jp = 0; jp < 4; jp++) {
                int nj = warpN * 64 + jp * 16;
                uint32_t bq[4];
                ldsm4t(bq, aB + ((ks * 16 + l15) * 136 + nj + lh) * 2);
                mma16(acc[0][2*jp],   af[0], bq);
                mma16(acc[0][2*jp+1], af[0], bq + 2);
                mma16(acc[1][2*jp],   af[1], bq);
                mma16(acc[1][2*jp+1], af[1], bq + 2);
            }
        }
        __syncthreads();
    }

    const float okscale = 0.03125f;   // (1024*1024)^-0.25
    #pragma unroll
    for (int i = 0; i < 2; i++) {
        #pragma unroll
        for (int j = 0; j < 8; j++) {
            #pragma unroll
            for (int cr = 0; cr < 4; cr++) {
                int m = m0 + warpM * 32 + i * 16 + g + (cr >> 1) * 8;
                int c = n0 + warpN * 64 + j * 8 + tg * 2 + (cr & 1);
                out[(size_t)m * DM + c] = acc[i][j][cr] * okscale + bias[c];
            }
        }
    }
}

// ---------------- launcher ---------------------------------------------------
extern "C" void kernel_launch(void* const* d_in, const int* in_sizes, int n_in,
                              void* d_out, int out_size)
{
    const float* inp = (const float*)d_in[0];   // (2, 2048, 1024)
    const float* qkv = (const float*)d_in[1];   // (1024, 3, 16, 64)
    const float* qb  = (const float*)d_in[2];   // (16, 64)
    const float* pos = (const float*)d_in[3];   // (256, 16, 64)
    const float* wk  = (const float*)d_in[4];   // (1024, 1024)
    const float* ob  = (const float*)d_in[5];   // (1024,)
    float* out = (float*)d_out;                 // (2, 2048, 1024)

    const int GEMM_SMEM = 35840 * 2;   // 71680 B (qkv/proj double buffers)
    const int AT_SMEM   = 20928 * 4;   // 83712 B -> 2 blocks/SM
    cudaFuncSetAttribute(qkv_kernel,
                         cudaFuncAttributeMaxDynamicSharedMemorySize, GEMM_SMEM);
    cudaFuncSetAttribute(proj_kernel,
                         cudaFuncAttributeMaxDynamicSharedMemorySize, GEMM_SMEM);
    cudaFuncSetAttribute(attn_kernel,
                         cudaFuncAttributeMaxDynamicSharedMemorySize, AT_SMEM);

    __half *d_inph, *d_wh, *d_wkh;
    cudaGetSymbolAddress((void**)&d_inph, g_inph);
    cudaGetSymbolAddress((void**)&d_wh,   g_wh);
    cudaGetSymbolAddress((void**)&d_wkh,  g_wkh);

    cvt_kernel<<<(BATCH*SEQ*DM/4 + 255)/256, 256>>>((const float4*)inp, (uint2*)d_inph, BATCH*SEQ*DM/4);
    cvt_kernel<<<(DM*BN3/4 + 255)/256, 256>>>((const float4*)qkv, (uint2*)d_wh, DM*BN3/4);
    cvt_kernel<<<(DM*DM/4 + 255)/256, 256>>>((const float4*)wk, (uint2*)d_wkh, DM*DM/4);

    qkv_kernel<<<dim3(BN3 / 128, (BATCH * SEQ) / 128), 256, GEMM_SMEM>>>(qb);
    emb_kernel<<<SEQ, 256>>>(pos);
    attn_kernel<<<dim3(SEQ / 64, BATCH * NHEAD), 256, AT_SMEM>>>();
    proj_kernel<<<dim3(DM / 128, (BATCH * SEQ) / 128), 256, GEMM_SMEM>>>(ob, out);
}